// round 2
// baseline (speedup 1.0000x reference)
#include <cuda_runtime.h>
#include <cstdint>

// Problem constants
#define B_ 4
#define N_ 4096
#define D_ 512
#define H_ 8
#define DH_ 64
#define M_ 128
#define TWOM_ 256

static constexpr int ROWS_TOT   = B_ * N_;            // 16384
static constexpr int BNH        = B_ * N_ * H_;       // 131072
static constexpr size_t PROJSZ  = (size_t)B_ * N_ * D_;        // 8388608 (=[B,N,H,DH])
static constexpr size_t QKPRSZ  = (size_t)B_ * N_ * H_ * TWOM_; // 33554432
static constexpr int KVS_SZ     = B_ * H_ * TWOM_ * DH_;        // 524288
static constexpr int KSPLIT     = 8;

// -------------------- scratch (device globals; no allocation allowed) ------
__device__ float g_val [PROJSZ];
__device__ float g_qpos[PROJSZ];   // holds pos_proj, then query_pos (in place)
__device__ float g_kpos[PROJSZ];   // holds slope_proj, then key_pos (in place)
__device__ float g_av  [PROJSZ];
__device__ float g_norm[BNH];
__device__ float g_kvs [KVS_SZ];
__device__ float g_kvs_part[KSPLIT * KVS_SZ];

// -------------------- fast sincos (Cody–Waite + cephes minimax) ------------
__device__ __forceinline__ void fast_sincos(float x, float& so, float& co) {
    const float INV_PIO2 = 0.63661977236758134308f;
    const float MAGIC    = 12582912.0f;           // 1.5 * 2^23
    const float PIO2_HI  = 1.57079637050628662109375f;
    const float PIO2_LO  = -4.371139000186243e-8f;
    float kf = fmaf(x, INV_PIO2, MAGIC);
    int   q  = __float_as_int(kf) & 3;
    kf -= MAGIC;
    float r = fmaf(-kf, PIO2_HI, x);
    r = fmaf(-kf, PIO2_LO, r);
    float r2 = r * r;
    // sin poly on [-pi/4, pi/4]
    float ps = -1.9515295891e-4f;
    ps = fmaf(ps, r2, 8.3321608736e-3f);
    ps = fmaf(ps, r2, -1.6666654611e-1f);
    float s = fmaf(ps * r2, r, r);
    // cos poly
    float pc = 2.443315711809948e-5f;
    pc = fmaf(pc, r2, -1.388731625493765e-3f);
    pc = fmaf(pc, r2, 4.166664568298827e-2f);
    float c = fmaf(pc, r2 * r2, fmaf(-0.5f, r2, 1.0f));
    float sv = (q & 1) ? c : s;
    float cv = (q & 1) ? s : c;
    if (q & 2)        sv = -sv;
    if ((q + 1) & 2)  cv = -cv;
    so = sv; co = cv;
}

// -------------------- GEMM NN: C[M,N] = A[M,K] * B[K,N] --------------------
// BM=128, BN=64, BK=16, TM=8, TN=8, 128 threads.
// Optional batch (z -> b=z/Hdim, h=z%Hdim) offsets and per-row scale on C.
__global__ __launch_bounds__(128) void gemm_nn_kernel(
    const float* __restrict__ A, const float* __restrict__ Bm, float* __restrict__ C,
    int K, int lda, int ldb, int ldc,
    long sAb, long sAh, long sBb, long sBh, long sCb, long sCh, int Hdim,
    const float* __restrict__ scaleBase, long sSb, long sSh, int scaleStride)
{
    int z = blockIdx.z;
    int zb = z / Hdim, zh = z % Hdim;
    A  += (size_t)zb * sAb + (size_t)zh * sAh;
    Bm += (size_t)zb * sBb + (size_t)zh * sBh;
    C  += (size_t)zb * sCb + (size_t)zh * sCh;
    const float* Sc = scaleBase ? (scaleBase + (size_t)zb * sSb + (size_t)zh * sSh) : nullptr;

    // Padded to 132 (528B row stride, still 16B-aligned): halves STS bank
    // conflicts in the transpose store (stride-512B 4-way -> 2-way).
    __shared__ float As[16][132];
    __shared__ float Bs[16][64];

    int tid = threadIdx.x;
    int tx = tid & 7;          // 0..7  -> col*8
    int ty = tid >> 3;         // 0..15 -> row*8
    int rowBase = blockIdx.x * 128;
    int colBase = blockIdx.y * 64;

    float acc[8][8];
#pragma unroll
    for (int i = 0; i < 8; i++)
#pragma unroll
        for (int j = 0; j < 8; j++) acc[i][j] = 0.f;

    for (int k0 = 0; k0 < K; k0 += 16) {
        // A tile 128x16 -> transposed into As[k][row]; 4 float4/thread
#pragma unroll
        for (int t = 0; t < 4; t++) {
            int f   = tid + t * 128;
            int row = f >> 2;
            int k4  = (f & 3) * 4;
            float4 v = *reinterpret_cast<const float4*>(A + (size_t)(rowBase + row) * lda + k0 + k4);
            As[k4 + 0][row] = v.x; As[k4 + 1][row] = v.y;
            As[k4 + 2][row] = v.z; As[k4 + 3][row] = v.w;
        }
        // B tile 16x64; 2 float4/thread
#pragma unroll
        for (int t = 0; t < 2; t++) {
            int f  = tid + t * 128;
            int kk = f >> 4;
            int n4 = (f & 15) * 4;
            *reinterpret_cast<float4*>(&Bs[kk][n4]) =
                *reinterpret_cast<const float4*>(Bm + (size_t)(k0 + kk) * ldb + colBase + n4);
        }
        __syncthreads();
#pragma unroll
        for (int kk = 0; kk < 16; kk++) {
            float a[8], b[8];
            *reinterpret_cast<float4*>(&a[0]) = *reinterpret_cast<float4*>(&As[kk][ty * 8]);
            *reinterpret_cast<float4*>(&a[4]) = *reinterpret_cast<float4*>(&As[kk][ty * 8 + 4]);
            *reinterpret_cast<float4*>(&b[0]) = *reinterpret_cast<float4*>(&Bs[kk][tx * 8]);
            *reinterpret_cast<float4*>(&b[4]) = *reinterpret_cast<float4*>(&Bs[kk][tx * 8 + 4]);
#pragma unroll
            for (int i = 0; i < 8; i++)
#pragma unroll
                for (int j = 0; j < 8; j++)
                    acc[i][j] = fmaf(a[i], b[j], acc[i][j]);
        }
        __syncthreads();
    }

#pragma unroll
    for (int i = 0; i < 8; i++) {
        int row = rowBase + ty * 8 + i;
        float s = Sc ? Sc[(size_t)row * scaleStride] : 1.0f;
        float* cp = C + (size_t)row * ldc + colBase + tx * 8;
        float4 o0, o1;
        o0.x = acc[i][0] * s; o0.y = acc[i][1] * s; o0.z = acc[i][2] * s; o0.w = acc[i][3] * s;
        o1.x = acc[i][4] * s; o1.y = acc[i][5] * s; o1.z = acc[i][6] * s; o1.w = acc[i][7] * s;
        *reinterpret_cast<float4*>(cp)     = o0;
        *reinterpret_cast<float4*>(cp + 4) = o1;
    }
}

// -------------------- GEMM TN (split-K): C[M,N] = A^T[M,K] * B[K,N] --------
// A stored [K, M] (lda), B [K, N] (ldb). BM=64, BN=64, BK=16, TM=4, TN=8.
// Writes partial result per K-split into Cpart (deterministic reduce later).
__global__ __launch_bounds__(128) void gemm_tn_kernel(
    const float* __restrict__ A, const float* __restrict__ Bm, float* __restrict__ Cpart,
    int K, int lda, int ldb,
    long sAb, long sAh, long sBb, long sBh, long sCb, long sCh, int Hdim)
{
    int z = blockIdx.z;
    int zb = z / Hdim, zh = z % Hdim;
    A  += (size_t)zb * sAb + (size_t)zh * sAh;
    Bm += (size_t)zb * sBb + (size_t)zh * sBh;
    float* C = Cpart + (size_t)blockIdx.y * KVS_SZ + (size_t)zb * sCb + (size_t)zh * sCh;

    __shared__ float As[16][64];
    __shared__ float Bs[16][64];

    int tid = threadIdx.x;
    int tx = tid & 7;           // col * 8
    int ty = tid >> 3;          // row * 4
    int m0 = blockIdx.x * 64;

    int kLen   = K / KSPLIT;
    int kStart = blockIdx.y * kLen;

    float acc[4][8];
#pragma unroll
    for (int i = 0; i < 4; i++)
#pragma unroll
        for (int j = 0; j < 8; j++) acc[i][j] = 0.f;

    for (int k0 = kStart; k0 < kStart + kLen; k0 += 16) {
#pragma unroll
        for (int t = 0; t < 2; t++) {
            int f  = tid + t * 128;
            int kk = f >> 4;
            int m4 = (f & 15) * 4;
            *reinterpret_cast<float4*>(&As[kk][m4]) =
                *reinterpret_cast<const float4*>(A + (size_t)(k0 + kk) * lda + m0 + m4);
        }
#pragma unroll
        for (int t = 0; t < 2; t++) {
            int f  = tid + t * 128;
            int kk = f >> 4;
            int n4 = (f & 15) * 4;
            *reinterpret_cast<float4*>(&Bs[kk][n4]) =
                *reinterpret_cast<const float4*>(Bm + (size_t)(k0 + kk) * ldb + n4);
        }
        __syncthreads();
#pragma unroll
        for (int kk = 0; kk < 16; kk++) {
            float a[4], b[8];
            *reinterpret_cast<float4*>(&a[0]) = *reinterpret_cast<float4*>(&As[kk][ty * 4]);
            *reinterpret_cast<float4*>(&b[0]) = *reinterpret_cast<float4*>(&Bs[kk][tx * 8]);
            *reinterpret_cast<float4*>(&b[4]) = *reinterpret_cast<float4*>(&Bs[kk][tx * 8 + 4]);
#pragma unroll
            for (int i = 0; i < 4; i++)
#pragma unroll
                for (int j = 0; j < 8; j++)
                    acc[i][j] = fmaf(a[i], b[j], acc[i][j]);
        }
        __syncthreads();
    }

#pragma unroll
    for (int i = 0; i < 4; i++) {
        float* cp = C + (size_t)(m0 + ty * 4 + i) * DH_ + tx * 8;
        float4 o0, o1;
        o0.x = acc[i][0]; o0.y = acc[i][1]; o0.z = acc[i][2]; o0.w = acc[i][3];
        o1.x = acc[i][4]; o1.y = acc[i][5]; o1.z = acc[i][6]; o1.w = acc[i][7];
        *reinterpret_cast<float4*>(cp)     = o0;
        *reinterpret_cast<float4*>(cp + 4) = o1;
    }
}

__global__ void kvs_reduce_kernel() {
    int i = blockIdx.x * 256 + threadIdx.x;
    if (i < KVS_SZ) {
        float s = 0.f;
#pragma unroll
        for (int p = 0; p < KSPLIT; p++) s += g_kvs_part[(size_t)p * KVS_SZ + i];
        g_kvs[i] = s;
    }
}

// -------------------- qpos/kpos/norm (in place on pos_proj / slope_proj) ---
__global__ __launch_bounds__(64) void posprep_kernel(
    const float* __restrict__ scale, const float* __restrict__ offs,
    float* __restrict__ qpos, float* __restrict__ kpos, float* __restrict__ norm)
{
    int rid = blockIdx.x;           // (b*N + n)*H + h
    int h   = rid & (H_ - 1);
    int d   = threadIdx.x;
    size_t idx = (size_t)rid * DH_ + d;
    float pp = qpos[idx];           // pos_proj
    float sp = kpos[idx];           // slope_proj
    float s  = scale[h];
    float o  = offs[h];
    float qp = s * pp;
    float kp = fmaf(o * s, sp, qp);
    qpos[idx] = qp;
    kpos[idx] = kp;
    float v = sp * sp;
#pragma unroll
    for (int off = 16; off > 0; off >>= 1)
        v += __shfl_xor_sync(0xffffffff, v, off);
    __shared__ float ws[2];
    if ((threadIdx.x & 31) == 0) ws[threadIdx.x >> 5] = v;
    __syncthreads();
    if (threadIdx.x == 0)
        norm[rid] = sqrtf(ws[0] + ws[1]) * (1.0f / (float)N_);
}

// -------------------- fourier features: dd = (dn*x)·projᵀ; [sin,cos]*ratio --
// Block: 256 threads, processes 16 (b,n,h)-rows for BOTH q and k.
__global__ __launch_bounds__(256) void fourier_kernel(
    const float* __restrict__ qpos, const float* __restrict__ kpos,
    const float* __restrict__ proj, float* __restrict__ qout, float* __restrict__ kout)
{
    __shared__ float projT[DH_][M_ + 4];   // [d][m], padded
    __shared__ float xs[2][16][DH_];

    const float DN    = 0.35355339059327378f;   // 64^-0.25
    const float RATIO = 0.08838834764831845f;   // 128^-0.5

    int tid = threadIdx.x;
    for (int i = tid; i < M_ * DH_; i += 256) {
        int m = i >> 6, d = i & 63;
        projT[d][m] = proj[i];
    }
    size_t rbase = (size_t)blockIdx.x * 16;
#pragma unroll
    for (int t = 0; t < 8; t++) {
        int i = tid + t * 256;                 // 0 .. 2047
        int side = i >> 10;
        int rr   = (i >> 6) & 15;
        int d    = i & 63;
        const float* src = side ? kpos : qpos;
        xs[side][rr][d] = DN * src[(rbase + rr) * DH_ + d];
    }
    __syncthreads();

    int u    = tid >> 5;        // 0..7
    int lane = tid & 31;
    int side = u >> 2;          // 0: q, 1: k
    int r0   = u & 3;
    int m4   = lane * 4;
    float* outBase = side ? kout : qout;

#pragma unroll 1
    for (int pass = 0; pass < 4; pass++) {
        int rr = pass * 4 + r0;
        const float* xv = xs[side][rr];
        float4 acc = make_float4(0.f, 0.f, 0.f, 0.f);
#pragma unroll
        for (int d = 0; d < DH_; d++) {
            float xd = xv[d];
            float4 p = *reinterpret_cast<const float4*>(&projT[d][m4]);
            acc.x = fmaf(xd, p.x, acc.x);
            acc.y = fmaf(xd, p.y, acc.y);
            acc.z = fmaf(xd, p.z, acc.z);
            acc.w = fmaf(xd, p.w, acc.w);
        }
        float s0, c0, s1, c1, s2, c2, s3, c3;
        fast_sincos(acc.x, s0, c0);
        fast_sincos(acc.y, s1, c1);
        fast_sincos(acc.z, s2, c2);
        fast_sincos(acc.w, s3, c3);
        float* op = outBase + (rbase + rr) * TWOM_;
        *reinterpret_cast<float4*>(op + m4)       = make_float4(RATIO * s0, RATIO * s1, RATIO * s2, RATIO * s3);
        *reinterpret_cast<float4*>(op + M_ + m4)  = make_float4(RATIO * c0, RATIO * c1, RATIO * c2, RATIO * c3);
    }
}

// -------------------- launch --------------------
extern "C" void kernel_launch(void* const* d_in, const int* in_sizes, int n_in,
                              void* d_out, int out_size)
{
    (void)in_sizes; (void)n_in; (void)out_size;
    const float* src  = (const float*)d_in[0];   // [B,N,D]
    const float* pf   = (const float*)d_in[1];   // [B,N,D]
    const float* pfs  = (const float*)d_in[2];   // [B,N,D]
    const float* vw   = (const float*)d_in[3];   // [D,H,DH] == [512,512]
    const float* pw   = (const float*)d_in[4];   // [D,H,DH]
    const float* sc   = (const float*)d_in[5];   // [H]
    const float* off  = (const float*)d_in[6];   // [H]
    const float* ow   = (const float*)d_in[7];   // [H*DH, D]
    const float* proj = (const float*)d_in[8];   // [M, DH]

    float* out  = (float*)d_out;                  // [B,N,D]
    float* qout = out + PROJSZ;                   // [B,N,H,2M]
    float* kout = qout + QKPRSZ;                  // [B,N,H,2M]

    float *val, *qp, *kp, *nr, *kvs, *kvsp, *av;
    cudaGetSymbolAddress((void**)&val,  g_val);
    cudaGetSymbolAddress((void**)&qp,   g_qpos);
    cudaGetSymbolAddress((void**)&kp,   g_kpos);
    cudaGetSymbolAddress((void**)&nr,   g_norm);
    cudaGetSymbolAddress((void**)&kvs,  g_kvs);
    cudaGetSymbolAddress((void**)&kvsp, g_kvs_part);
    cudaGetSymbolAddress((void**)&av,   g_av);

    dim3 gBig(ROWS_TOT / 128, D_ / 64, 1);

    // 1-3: projections
    gemm_nn_kernel<<<gBig, 128>>>(src, vw, val, D_, D_, D_, D_,
                                  0,0,0,0,0,0, 1, nullptr, 0,0,0);
    gemm_nn_kernel<<<gBig, 128>>>(pf,  pw, qp,  D_, D_, D_, D_,
                                  0,0,0,0,0,0, 1, nullptr, 0,0,0);
    gemm_nn_kernel<<<gBig, 128>>>(pfs, pw, kp,  D_, D_, D_, D_,
                                  0,0,0,0,0,0, 1, nullptr, 0,0,0);

    // 4: scale/offset + norms (in place)
    posprep_kernel<<<BNH, 64>>>(sc, off, qp, kp, nr);

    // 5: fourier features -> q_prime / k_prime (directly into d_out)
    fourier_kernel<<<BNH / 16, 256>>>(qp, kp, proj, qout, kout);

    // 6: kvs = k'^T @ V  per (b,h), split-K partials + reduce
    {
        long sAb = (long)N_ * H_ * TWOM_;  // 8388608
        long sAh = TWOM_;                  // 256
        long sBb = (long)N_ * H_ * DH_;    // 2097152
        long sBh = DH_;                    // 64
        long sCb = (long)H_ * TWOM_ * DH_; // 131072
        long sCh = (long)TWOM_ * DH_;      // 16384
        dim3 g(TWOM_ / 64, KSPLIT, B_ * H_);
        gemm_tn_kernel<<<g, 128>>>(kout, val, kvsp, N_, (long)H_ * TWOM_, (long)H_ * DH_,
                                   sAb, sAh, sBb, sBh, sCb, sCh, H_);
        kvs_reduce_kernel<<<(KVS_SZ + 255) / 256, 256>>>();
    }

    // 7: av = norm * (q' @ kvs)  per (b,h)
    {
        long sAb = (long)N_ * H_ * TWOM_;
        long sAh = TWOM_;
        long sBb = (long)H_ * TWOM_ * DH_;
        long sBh = (long)TWOM_ * DH_;
        long sCb = (long)N_ * H_ * DH_;
        long sCh = DH_;
        long sSb = (long)N_ * H_;
        long sSh = 1;
        dim3 g(N_ / 128, 1, B_ * H_);
        gemm_nn_kernel<<<g, 128>>>(qout, kvs, av, TWOM_,
                                   H_ * TWOM_, DH_, H_ * DH_,
                                   sAb, sAh, sBb, sBh, sCb, sCh, H_,
                                   nr, sSb, sSh, H_);
    }

    // 8: out = av_flat @ output_weight
    gemm_nn_kernel<<<gBig, 128>>>(av, ow, out, D_, D_, D_, D_,
                                  0,0,0,0,0,0, 1, nullptr, 0,0,0);
}

// round 3
// speedup vs baseline: 1.1132x; 1.1132x over previous
#include <cuda_runtime.h>
#include <cstdint>

// Problem constants
#define B_ 4
#define N_ 4096
#define D_ 512
#define H_ 8
#define DH_ 64
#define M_ 128
#define TWOM_ 256

static constexpr int ROWS_TOT   = B_ * N_;            // 16384
static constexpr int BNH        = B_ * N_ * H_;       // 131072
static constexpr size_t PROJSZ  = (size_t)B_ * N_ * D_;         // 8388608
static constexpr size_t QKPRSZ  = (size_t)B_ * N_ * H_ * TWOM_; // 33554432
static constexpr int KVS_SZ     = B_ * H_ * TWOM_ * DH_;        // 524288
static constexpr int KSPLIT     = 8;

// -------------------- scratch (device globals) -----------------------------
__device__ float g_val [PROJSZ];
__device__ float g_pp  [PROJSZ];   // raw pos_proj
__device__ float g_sp  [PROJSZ];   // raw slope_proj
__device__ float g_av  [PROJSZ];
__device__ float g_norm[BNH];
__device__ float g_kvs [KVS_SZ];
__device__ float g_kvs_part[KSPLIT * KVS_SZ];

// -------------------- fast sincos ------------------------------------------
__device__ __forceinline__ void fast_sincos(float x, float& so, float& co) {
    const float INV_PIO2 = 0.63661977236758134308f;
    const float MAGIC    = 12582912.0f;
    const float PIO2_HI  = 1.57079637050628662109375f;
    const float PIO2_LO  = -4.371139000186243e-8f;
    float kf = fmaf(x, INV_PIO2, MAGIC);
    int   q  = __float_as_int(kf) & 3;
    kf -= MAGIC;
    float r = fmaf(-kf, PIO2_HI, x);
    r = fmaf(-kf, PIO2_LO, r);
    float r2 = r * r;
    float ps = -1.9515295891e-4f;
    ps = fmaf(ps, r2, 8.3321608736e-3f);
    ps = fmaf(ps, r2, -1.6666654611e-1f);
    float s = fmaf(ps * r2, r, r);
    float pc = 2.443315711809948e-5f;
    pc = fmaf(pc, r2, -1.388731625493765e-3f);
    pc = fmaf(pc, r2, 4.166664568298827e-2f);
    float c = fmaf(pc, r2 * r2, fmaf(-0.5f, r2, 1.0f));
    float sv = (q & 1) ? c : s;
    float cv = (q & 1) ? s : c;
    if (q & 2)        sv = -sv;
    if ((q + 1) & 2)  cv = -cv;
    so = sv; co = cv;
}

// -------------------- tf32 helpers -----------------------------------------
__device__ __forceinline__ uint32_t f2tf(float x) {
    uint32_t r;
    asm("cvt.rna.tf32.f32 %0, %1;" : "=r"(r) : "f"(x));
    return r;
}
__device__ __forceinline__ void split_tf32(float x, float& h, float& l) {
    uint32_t hu = f2tf(x);
    h = __uint_as_float(hu);
    float r = x - h;
    l = __uint_as_float(f2tf(r));
}
__device__ __forceinline__ void mma8(float* c, const uint32_t* a, uint32_t b0, uint32_t b1) {
    asm volatile(
        "mma.sync.aligned.m16n8k8.row.col.f32.tf32.tf32.f32 "
        "{%0,%1,%2,%3}, {%4,%5,%6,%7}, {%8,%9}, {%0,%1,%2,%3};"
        : "+f"(c[0]), "+f"(c[1]), "+f"(c[2]), "+f"(c[3])
        : "r"(a[0]), "r"(a[1]), "r"(a[2]), "r"(a[3]), "r"(b0), "r"(b1));
}

// -------------------- tf32 3x-split GEMM NN --------------------------------
// C[M,N] = A[M,K] * B[K,N], fp32 in/out, fp32-accurate via hi/lo tf32 split.
// BM=128, BK=16, 256 threads (8 warps). BN=128: warp tile 64x32 (2m x 4n).
// BN=64: warp tile 32x32 (4m x 2n). Double-buffered dynamic smem.
template<int BN>
__global__ __launch_bounds__(256) void gemm_tf32_nn(
    const float* __restrict__ A, const float* __restrict__ Bm, float* __restrict__ C,
    int K, int lda, int ldb, int ldc,
    long sAb, long sAh, long sBb, long sBh, long sCb, long sCh, int Hdim,
    const float* __restrict__ scaleBase, long sSb, long sSh, int scaleStride)
{
    constexpr int APITCH = 20;
    constexpr int BPITCH = BN + 8;
    constexpr int ASTG   = 128 * APITCH;      // floats
    constexpr int BSTG   = 16 * BPITCH;
    constexpr int STAGE  = 2 * ASTG + 2 * BSTG;
    constexpr int NW     = BN / 32;           // n-warps
    constexpr int MT     = (BN == 128) ? 4 : 2;  // m16 tiles per warp

    extern __shared__ float smx[];

    int z = blockIdx.z;
    int zb = z / Hdim, zh = z % Hdim;
    A  += (size_t)zb * sAb + (size_t)zh * sAh;
    Bm += (size_t)zb * sBb + (size_t)zh * sBh;
    C  += (size_t)zb * sCb + (size_t)zh * sCh;
    const float* Sc = scaleBase ? (scaleBase + (size_t)zb * sSb + (size_t)zh * sSh) : nullptr;

    const int tid  = threadIdx.x;
    const int warp = tid >> 5, lane = tid & 31;
    const int g = lane >> 2, tg = lane & 3;
    const int wn = warp % NW, wm = warp / NW;

    const int rowBase = blockIdx.x * 128;
    const int colBase = blockIdx.y * BN;

    // staging thread mapping
    const int ar = tid >> 2;               // A row (0..63; +64 second)
    const int ak = (tid & 3) * 4;          // A k within tile
    const int bkk = (BN == 128) ? (tid >> 5) : (tid >> 4);
    const int bnn = (BN == 128) ? ((tid & 31) * 4) : ((tid & 15) * 4);

    float4 ra0, ra1, rb0, rb1;

    auto ldg = [&](int k0) {
        ra0 = *reinterpret_cast<const float4*>(A + (size_t)(rowBase + ar)      * lda + k0 + ak);
        ra1 = *reinterpret_cast<const float4*>(A + (size_t)(rowBase + ar + 64) * lda + k0 + ak);
        rb0 = *reinterpret_cast<const float4*>(Bm + (size_t)(k0 + bkk) * ldb + colBase + bnn);
        if (BN == 128)
            rb1 = *reinterpret_cast<const float4*>(Bm + (size_t)(k0 + bkk + 8) * ldb + colBase + bnn);
    };

    auto st4 = [&](float* hi, float* lo, float4 v) {
        float4 h, l;
        split_tf32(v.x, h.x, l.x); split_tf32(v.y, h.y, l.y);
        split_tf32(v.z, h.z, l.z); split_tf32(v.w, h.w, l.w);
        *reinterpret_cast<float4*>(hi) = h;
        *reinterpret_cast<float4*>(lo) = l;
    };

    auto split_store = [&](float* base) {
        float* Ah = base;
        float* Al = base + ASTG;
        float* Bh = base + 2 * ASTG;
        float* Bl = Bh + BSTG;
        st4(Ah + ar * APITCH + ak,        Al + ar * APITCH + ak,        ra0);
        st4(Ah + (ar + 64) * APITCH + ak, Al + (ar + 64) * APITCH + ak, ra1);
        st4(Bh + bkk * BPITCH + bnn,      Bl + bkk * BPITCH + bnn,      rb0);
        if (BN == 128)
            st4(Bh + (bkk + 8) * BPITCH + bnn, Bl + (bkk + 8) * BPITCH + bnn, rb1);
    };

    float acc[MT][4][4];
#pragma unroll
    for (int i = 0; i < MT; i++)
#pragma unroll
        for (int j = 0; j < 4; j++)
#pragma unroll
            for (int k = 0; k < 4; k++) acc[i][j][k] = 0.f;

    auto compute = [&](const float* base) {
        const float* Ah = base;
        const float* Al = base + ASTG;
        const float* Bh = base + 2 * ASTG;
        const float* Bl = Bh + BSTG;
        const int rw = wm * (MT * 16) + g;
        const int cw = wn * 32 + g;
#pragma unroll
        for (int ks = 0; ks < 2; ks++) {
            const int kb = ks * 8;
            uint32_t af[MT][4];
            // pass 1: A_hi x (B_hi + B_lo)
#pragma unroll
            for (int mt = 0; mt < MT; mt++) {
                const float* p = Ah + (size_t)(rw + mt * 16) * APITCH + kb + tg;
                af[mt][0] = __float_as_uint(p[0]);
                af[mt][1] = __float_as_uint(p[8 * APITCH]);
                af[mt][2] = __float_as_uint(p[4]);
                af[mt][3] = __float_as_uint(p[8 * APITCH + 4]);
            }
#pragma unroll
            for (int nt = 0; nt < 4; nt++) {
                const float* q  = Bh + (size_t)(kb + tg) * BPITCH + cw + nt * 8;
                const float* ql = Bl + (size_t)(kb + tg) * BPITCH + cw + nt * 8;
                uint32_t b0 = __float_as_uint(q[0]);
                uint32_t b1 = __float_as_uint(q[4 * BPITCH]);
                uint32_t l0 = __float_as_uint(ql[0]);
                uint32_t l1 = __float_as_uint(ql[4 * BPITCH]);
#pragma unroll
                for (int mt = 0; mt < MT; mt++) {
                    mma8(acc[mt][nt], af[mt], l0, l1);
                    mma8(acc[mt][nt], af[mt], b0, b1);
                }
            }
            // pass 2: A_lo x B_hi
#pragma unroll
            for (int mt = 0; mt < MT; mt++) {
                const float* p = Al + (size_t)(rw + mt * 16) * APITCH + kb + tg;
                af[mt][0] = __float_as_uint(p[0]);
                af[mt][1] = __float_as_uint(p[8 * APITCH]);
                af[mt][2] = __float_as_uint(p[4]);
                af[mt][3] = __float_as_uint(p[8 * APITCH + 4]);
            }
#pragma unroll
            for (int nt = 0; nt < 4; nt++) {
                const float* q = Bh + (size_t)(kb + tg) * BPITCH + cw + nt * 8;
                uint32_t b0 = __float_as_uint(q[0]);
                uint32_t b1 = __float_as_uint(q[4 * BPITCH]);
#pragma unroll
                for (int mt = 0; mt < MT; mt++)
                    mma8(acc[mt][nt], af[mt], b0, b1);
            }
        }
    };

    const int nIter = K / 16;
    ldg(0);
    split_store(smx);
    __syncthreads();
    for (int it = 0; it < nIter; it++) {
        const int cur = it & 1;
        if (it + 1 < nIter) ldg((it + 1) * 16);
        compute(smx + cur * STAGE);
        if (it + 1 < nIter) split_store(smx + (cur ^ 1) * STAGE);
        __syncthreads();
    }

    // epilogue
#pragma unroll
    for (int mt = 0; mt < MT; mt++) {
        int r0 = rowBase + wm * (MT * 16) + mt * 16 + g;
        float s0 = Sc ? Sc[(size_t)r0 * scaleStride] : 1.0f;
        float s1 = Sc ? Sc[(size_t)(r0 + 8) * scaleStride] : 1.0f;
#pragma unroll
        for (int nt = 0; nt < 4; nt++) {
            int cc = colBase + wn * 32 + nt * 8 + 2 * tg;
            float2 v0, v1;
            v0.x = acc[mt][nt][0] * s0; v0.y = acc[mt][nt][1] * s0;
            v1.x = acc[mt][nt][2] * s1; v1.y = acc[mt][nt][3] * s1;
            *reinterpret_cast<float2*>(C + (size_t)r0 * ldc + cc)       = v0;
            *reinterpret_cast<float2*>(C + (size_t)(r0 + 8) * ldc + cc) = v1;
        }
    }
}

// -------------------- GEMM TN (split-K, fp32 SIMT): kvs --------------------
__global__ __launch_bounds__(128) void gemm_tn_kernel(
    const float* __restrict__ A, const float* __restrict__ Bm, float* __restrict__ Cpart,
    int K, int lda, int ldb,
    long sAb, long sAh, long sBb, long sBh, long sCb, long sCh, int Hdim)
{
    int z = blockIdx.z;
    int zb = z / Hdim, zh = z % Hdim;
    A  += (size_t)zb * sAb + (size_t)zh * sAh;
    Bm += (size_t)zb * sBb + (size_t)zh * sBh;
    float* C = Cpart + (size_t)blockIdx.y * KVS_SZ + (size_t)zb * sCb + (size_t)zh * sCh;

    __shared__ float As[16][64];
    __shared__ float Bs[16][64];

    int tid = threadIdx.x;
    int tx = tid & 7;
    int ty = tid >> 3;
    int m0 = blockIdx.x * 64;

    int kLen   = K / KSPLIT;
    int kStart = blockIdx.y * kLen;

    float acc[4][8];
#pragma unroll
    for (int i = 0; i < 4; i++)
#pragma unroll
        for (int j = 0; j < 8; j++) acc[i][j] = 0.f;

    for (int k0 = kStart; k0 < kStart + kLen; k0 += 16) {
#pragma unroll
        for (int t = 0; t < 2; t++) {
            int f  = tid + t * 128;
            int kk = f >> 4;
            int m4 = (f & 15) * 4;
            *reinterpret_cast<float4*>(&As[kk][m4]) =
                *reinterpret_cast<const float4*>(A + (size_t)(k0 + kk) * lda + m0 + m4);
        }
#pragma unroll
        for (int t = 0; t < 2; t++) {
            int f  = tid + t * 128;
            int kk = f >> 4;
            int n4 = (f & 15) * 4;
            *reinterpret_cast<float4*>(&Bs[kk][n4]) =
                *reinterpret_cast<const float4*>(Bm + (size_t)(k0 + kk) * ldb + n4);
        }
        __syncthreads();
#pragma unroll
        for (int kk = 0; kk < 16; kk++) {
            float a[4], b[8];
            *reinterpret_cast<float4*>(&a[0]) = *reinterpret_cast<float4*>(&As[kk][ty * 4]);
            *reinterpret_cast<float4*>(&b[0]) = *reinterpret_cast<float4*>(&Bs[kk][tx * 8]);
            *reinterpret_cast<float4*>(&b[4]) = *reinterpret_cast<float4*>(&Bs[kk][tx * 8 + 4]);
#pragma unroll
            for (int i = 0; i < 4; i++)
#pragma unroll
                for (int j = 0; j < 8; j++)
                    acc[i][j] = fmaf(a[i], b[j], acc[i][j]);
        }
        __syncthreads();
    }

#pragma unroll
    for (int i = 0; i < 4; i++) {
        float* cp = C + (size_t)(m0 + ty * 4 + i) * DH_ + tx * 8;
        float4 o0, o1;
        o0.x = acc[i][0]; o0.y = acc[i][1]; o0.z = acc[i][2]; o0.w = acc[i][3];
        o1.x = acc[i][4]; o1.y = acc[i][5]; o1.z = acc[i][6]; o1.w = acc[i][7];
        *reinterpret_cast<float4*>(cp)     = o0;
        *reinterpret_cast<float4*>(cp + 4) = o1;
    }
}

__global__ void kvs_reduce_kernel() {
    int i = blockIdx.x * 256 + threadIdx.x;
    if (i < KVS_SZ) {
        float s = 0.f;
#pragma unroll
        for (int p = 0; p < KSPLIT; p++) s += g_kvs_part[(size_t)p * KVS_SZ + i];
        g_kvs[i] = s;
    }
}

// -------------------- fourier + fused posprep ------------------------------
// Reads RAW pos_proj / slope_proj, applies scale/offset in registers, computes
// slope-norms, then dd GEMV + sincos into q'/k'.
__global__ __launch_bounds__(256) void fourier_kernel(
    const float* __restrict__ ppraw, const float* __restrict__ spraw,
    const float* __restrict__ scale, const float* __restrict__ offs,
    const float* __restrict__ proj, float* __restrict__ qout,
    float* __restrict__ kout, float* __restrict__ norm)
{
    __shared__ float projT[DH_][M_ + 4];   // [d][m]
    __shared__ float xs[2][16][DH_];

    const float DN    = 0.35355339059327378f;   // 64^-0.25
    const float RATIO = 0.08838834764831845f;   // 128^-0.5

    int tid = threadIdx.x;
    for (int i = tid; i < M_ * DH_; i += 256) {
        int m = i >> 6, d = i & 63;
        projT[d][m] = proj[i];
    }

    size_t rbase = (size_t)blockIdx.x * 16;
    {
        int rr = tid >> 4;
        int d0 = (tid & 15) * 4;
        size_t rid = rbase + rr;
        int h = (int)(rid & (H_ - 1));
        float s = scale[h];
        float o = offs[h];
        float4 pp = *reinterpret_cast<const float4*>(ppraw + rid * DH_ + d0);
        float4 sp = *reinterpret_cast<const float4*>(spraw + rid * DH_ + d0);
        float4 q4, k4;
        q4.x = s * pp.x; q4.y = s * pp.y; q4.z = s * pp.z; q4.w = s * pp.w;
        float os = o * s;
        k4.x = fmaf(os, sp.x, q4.x); k4.y = fmaf(os, sp.y, q4.y);
        k4.z = fmaf(os, sp.z, q4.z); k4.w = fmaf(os, sp.w, q4.w);
        float4 xq, xk;
        xq.x = DN * q4.x; xq.y = DN * q4.y; xq.z = DN * q4.z; xq.w = DN * q4.w;
        xk.x = DN * k4.x; xk.y = DN * k4.y; xk.z = DN * k4.z; xk.w = DN * k4.w;
        *reinterpret_cast<float4*>(&xs[0][rr][d0]) = xq;
        *reinterpret_cast<float4*>(&xs[1][rr][d0]) = xk;
        float sq = sp.x * sp.x + sp.y * sp.y + sp.z * sp.z + sp.w * sp.w;
#pragma unroll
        for (int m = 8; m > 0; m >>= 1)
            sq += __shfl_xor_sync(0xffffffff, sq, m);
        if ((tid & 15) == 0)
            norm[rid] = sqrtf(sq) * (1.0f / (float)N_);
    }
    __syncthreads();

    int u    = tid >> 5;
    int lane = tid & 31;
    int side = u >> 2;
    int r0   = u & 3;
    int m4   = lane * 4;
    float* outBase = side ? kout : qout;

#pragma unroll 1
    for (int pass = 0; pass < 4; pass++) {
        int rr = pass * 4 + r0;
        const float* xv = xs[side][rr];
        float4 acc = make_float4(0.f, 0.f, 0.f, 0.f);
#pragma unroll
        for (int d = 0; d < DH_; d++) {
            float xd = xv[d];
            float4 p = *reinterpret_cast<const float4*>(&projT[d][m4]);
            acc.x = fmaf(xd, p.x, acc.x);
            acc.y = fmaf(xd, p.y, acc.y);
            acc.z = fmaf(xd, p.z, acc.z);
            acc.w = fmaf(xd, p.w, acc.w);
        }
        float s0, c0, s1, c1, s2, c2, s3, c3;
        fast_sincos(acc.x, s0, c0);
        fast_sincos(acc.y, s1, c1);
        fast_sincos(acc.z, s2, c2);
        fast_sincos(acc.w, s3, c3);
        float* op = outBase + (rbase + rr) * TWOM_;
        *reinterpret_cast<float4*>(op + m4)      = make_float4(RATIO * s0, RATIO * s1, RATIO * s2, RATIO * s3);
        *reinterpret_cast<float4*>(op + M_ + m4) = make_float4(RATIO * c0, RATIO * c1, RATIO * c2, RATIO * c3);
    }
}

// -------------------- launch -----------------------------------------------
extern "C" void kernel_launch(void* const* d_in, const int* in_sizes, int n_in,
                              void* d_out, int out_size)
{
    (void)in_sizes; (void)n_in; (void)out_size;
    const float* src  = (const float*)d_in[0];
    const float* pf   = (const float*)d_in[1];
    const float* pfs  = (const float*)d_in[2];
    const float* vw   = (const float*)d_in[3];
    const float* pw   = (const float*)d_in[4];
    const float* sc   = (const float*)d_in[5];
    const float* off  = (const float*)d_in[6];
    const float* ow   = (const float*)d_in[7];
    const float* proj = (const float*)d_in[8];

    float* out  = (float*)d_out;
    float* qout = out + PROJSZ;
    float* kout = qout + QKPRSZ;

    float *val, *pp, *sp, *nr, *kvs, *kvsp, *av;
    cudaGetSymbolAddress((void**)&val,  g_val);
    cudaGetSymbolAddress((void**)&pp,   g_pp);
    cudaGetSymbolAddress((void**)&sp,   g_sp);
    cudaGetSymbolAddress((void**)&nr,   g_norm);
    cudaGetSymbolAddress((void**)&kvs,  g_kvs);
    cudaGetSymbolAddress((void**)&kvsp, g_kvs_part);
    cudaGetSymbolAddress((void**)&av,   g_av);

    // dynamic smem sizes (double-buffered)
    const int SM128 = (2 * 128 * 20 + 2 * 16 * 136) * 4 * 2;  // 75776 B
    const int SM64  = (2 * 128 * 20 + 2 * 16 * 72)  * 4 * 2;  // 59392 B
    cudaFuncSetAttribute(gemm_tf32_nn<128>, cudaFuncAttributeMaxDynamicSharedMemorySize, SM128);
    cudaFuncSetAttribute(gemm_tf32_nn<64>,  cudaFuncAttributeMaxDynamicSharedMemorySize, SM64);

    dim3 gBig(ROWS_TOT / 128, D_ / 128, 1);

    // 1-3: projections (tf32 tensor)
    gemm_tf32_nn<128><<<gBig, 256, SM128>>>(src, vw, val, D_, D_, D_, D_,
                                            0,0,0,0,0,0, 1, nullptr, 0,0,0);
    gemm_tf32_nn<128><<<gBig, 256, SM128>>>(pf,  pw, pp,  D_, D_, D_, D_,
                                            0,0,0,0,0,0, 1, nullptr, 0,0,0);
    gemm_tf32_nn<128><<<gBig, 256, SM128>>>(pfs, pw, sp,  D_, D_, D_, D_,
                                            0,0,0,0,0,0, 1, nullptr, 0,0,0);

    // 4: fourier (fused posprep + norms) -> q'/k' into d_out
    fourier_kernel<<<BNH / 16, 256>>>(pp, sp, sc, off, proj, qout, kout, nr);

    // 5: kvs = k'^T @ V per (b,h): split-K partials + deterministic reduce
    {
        long sAb = (long)N_ * H_ * TWOM_;
        long sAh = TWOM_;
        long sBb = (long)N_ * H_ * DH_;
        long sBh = DH_;
        long sCb = (long)H_ * TWOM_ * DH_;
        long sCh = (long)TWOM_ * DH_;
        dim3 g(TWOM_ / 64, KSPLIT, B_ * H_);
        gemm_tn_kernel<<<g, 128>>>(kout, val, kvsp, N_, (long)H_ * TWOM_, (long)H_ * DH_,
                                   sAb, sAh, sBb, sBh, sCb, sCh, H_);
        kvs_reduce_kernel<<<(KVS_SZ + 255) / 256, 256>>>();
    }

    // 6: av = norm * (q' @ kvs) per (b,h) (tf32 tensor, BN=64)
    {
        long sAb = (long)N_ * H_ * TWOM_;
        long sAh = TWOM_;
        long sBb = (long)H_ * TWOM_ * DH_;
        long sBh = (long)TWOM_ * DH_;
        long sCb = (long)N_ * H_ * DH_;
        long sCh = DH_;
        long sSb = (long)N_ * H_;
        long sSh = 1;
        dim3 g(N_ / 128, 1, B_ * H_);
        gemm_tf32_nn<64><<<g, 256, SM64>>>(qout, kvs, av, TWOM_,
                                           H_ * TWOM_, DH_, H_ * DH_,
                                           sAb, sAh, sBb, sBh, sCb, sCh, H_,
                                           nr, sSb, sSh, H_);
    }

    // 7: out = av_flat @ output_weight (tf32 tensor)
    gemm_tf32_nn<128><<<gBig, 256, SM128>>>(av, ow, out, D_, D_, D_, D_,
                                            0,0,0,0,0,0, 1, nullptr, 0,0,0);
}

// round 5
// speedup vs baseline: 1.3654x; 1.2266x over previous
#include <cuda_runtime.h>
#include <cstdint>

// Problem constants
#define B_ 4
#define N_ 4096
#define D_ 512
#define H_ 8
#define DH_ 64
#define M_ 128
#define TWOM_ 256

static constexpr int ROWS_TOT   = B_ * N_;            // 16384
static constexpr int BNH        = B_ * N_ * H_;       // 131072
static constexpr size_t PROJSZ  = (size_t)B_ * N_ * D_;         // 8388608
static constexpr size_t QKPRSZ  = (size_t)B_ * N_ * H_ * TWOM_; // 33554432
static constexpr int KVS_SZ     = B_ * H_ * TWOM_ * DH_;        // 524288
static constexpr int KSPLIT     = 8;

// -------------------- scratch (device globals) -----------------------------
__device__ float g_val [PROJSZ];
__device__ float g_pp  [PROJSZ];   // raw pos_proj
__device__ float g_sp  [PROJSZ];   // raw slope_proj
__device__ float g_av  [PROJSZ];
__device__ float g_norm[BNH];
__device__ float g_kvs [KVS_SZ];
__device__ float g_kvs_part[KSPLIT * KVS_SZ];

// -------------------- fast sincos ------------------------------------------
__device__ __forceinline__ void fast_sincos(float x, float& so, float& co) {
    const float INV_PIO2 = 0.63661977236758134308f;
    const float MAGIC    = 12582912.0f;
    const float PIO2_HI  = 1.57079637050628662109375f;
    const float PIO2_LO  = -4.371139000186243e-8f;
    float kf = fmaf(x, INV_PIO2, MAGIC);
    int   q  = __float_as_int(kf) & 3;
    kf -= MAGIC;
    float r = fmaf(-kf, PIO2_HI, x);
    r = fmaf(-kf, PIO2_LO, r);
    float r2 = r * r;
    float ps = -1.9515295891e-4f;
    ps = fmaf(ps, r2, 8.3321608736e-3f);
    ps = fmaf(ps, r2, -1.6666654611e-1f);
    float s = fmaf(ps * r2, r, r);
    float pc = 2.443315711809948e-5f;
    pc = fmaf(pc, r2, -1.388731625493765e-3f);
    pc = fmaf(pc, r2, 4.166664568298827e-2f);
    float c = fmaf(pc, r2 * r2, fmaf(-0.5f, r2, 1.0f));
    float sv = (q & 1) ? c : s;
    float cv = (q & 1) ? s : c;
    if (q & 2)        sv = -sv;
    if ((q + 1) & 2)  cv = -cv;
    so = sv; co = cv;
}

// -------------------- tf32 helpers -----------------------------------------
__device__ __forceinline__ uint32_t f2tf(float x) {
    uint32_t r;
    asm("cvt.rna.tf32.f32 %0, %1;" : "=r"(r) : "f"(x));
    return r;
}
__device__ __forceinline__ void split_tf32(float x, float& h, float& l) {
    uint32_t hu = f2tf(x);
    h = __uint_as_float(hu);
    float r = x - h;
    l = __uint_as_float(f2tf(r));
}
__device__ __forceinline__ void mma8(float* c, const uint32_t* a, uint32_t b0, uint32_t b1) {
    asm volatile(
        "mma.sync.aligned.m16n8k8.row.col.f32.tf32.tf32.f32 "
        "{%0,%1,%2,%3}, {%4,%5,%6,%7}, {%8,%9}, {%0,%1,%2,%3};"
        : "+f"(c[0]), "+f"(c[1]), "+f"(c[2]), "+f"(c[3])
        : "r"(a[0]), "r"(a[1]), "r"(a[2]), "r"(a[3]), "r"(b0), "r"(b1));
}

// -------------------- tf32 3x-split GEMM NN --------------------------------
// C[M,N] = A[M,K] * B[K,N], fp32 in/out, fp32-accurate via hi/lo tf32 split.
// BM=128, BK=16, 256 threads (8 warps), 2 blocks/SM for latency hiding.
template<int BN>
__global__ __launch_bounds__(256, 2) void gemm_tf32_nn(
    const float* __restrict__ A, const float* __restrict__ Bm, float* __restrict__ C,
    int K, int lda, int ldb, int ldc,
    long sAb, long sAh, long sBb, long sBh, long sCb, long sCh, int Hdim,
    const float* __restrict__ scaleBase, long sSb, long sSh, int scaleStride)
{
    constexpr int APITCH = 20;
    constexpr int BPITCH = BN + 8;
    constexpr int ASTG   = 128 * APITCH;      // floats
    constexpr int BSTG   = 16 * BPITCH;
    constexpr int STAGE  = 2 * ASTG + 2 * BSTG;
    constexpr int NW     = BN / 32;           // n-warps
    constexpr int MT     = (BN == 128) ? 4 : 2;  // m16 tiles per warp

    extern __shared__ float smx[];

    int z = blockIdx.z;
    int zb = z / Hdim, zh = z % Hdim;
    A  += (size_t)zb * sAb + (size_t)zh * sAh;
    Bm += (size_t)zb * sBb + (size_t)zh * sBh;
    C  += (size_t)zb * sCb + (size_t)zh * sCh;
    const float* Sc = scaleBase ? (scaleBase + (size_t)zb * sSb + (size_t)zh * sSh) : nullptr;

    const int tid  = threadIdx.x;
    const int warp = tid >> 5, lane = tid & 31;
    const int g = lane >> 2, tg = lane & 3;
    const int wn = warp % NW, wm = warp / NW;

    const int rowBase = blockIdx.x * 128;
    const int colBase = blockIdx.y * BN;

    const int ar = tid >> 2;
    const int ak = (tid & 3) * 4;
    const int bkk = (BN == 128) ? (tid >> 5) : (tid >> 4);
    const int bnn = (BN == 128) ? ((tid & 31) * 4) : ((tid & 15) * 4);

    float4 ra0, ra1, rb0, rb1;

    auto ldg = [&](int k0) {
        ra0 = *reinterpret_cast<const float4*>(A + (size_t)(rowBase + ar)      * lda + k0 + ak);
        ra1 = *reinterpret_cast<const float4*>(A + (size_t)(rowBase + ar + 64) * lda + k0 + ak);
        rb0 = *reinterpret_cast<const float4*>(Bm + (size_t)(k0 + bkk) * ldb + colBase + bnn);
        if (BN == 128)
            rb1 = *reinterpret_cast<const float4*>(Bm + (size_t)(k0 + bkk + 8) * ldb + colBase + bnn);
    };

    auto st4 = [&](float* hi, float* lo, float4 v) {
        float4 h, l;
        split_tf32(v.x, h.x, l.x); split_tf32(v.y, h.y, l.y);
        split_tf32(v.z, h.z, l.z); split_tf32(v.w, h.w, l.w);
        *reinterpret_cast<float4*>(hi) = h;
        *reinterpret_cast<float4*>(lo) = l;
    };

    auto split_store = [&](float* base) {
        float* Ah = base;
        float* Al = base + ASTG;
        float* Bh = base + 2 * ASTG;
        float* Bl = Bh + BSTG;
        st4(Ah + ar * APITCH + ak,        Al + ar * APITCH + ak,        ra0);
        st4(Ah + (ar + 64) * APITCH + ak, Al + (ar + 64) * APITCH + ak, ra1);
        st4(Bh + bkk * BPITCH + bnn,      Bl + bkk * BPITCH + bnn,      rb0);
        if (BN == 128)
            st4(Bh + (bkk + 8) * BPITCH + bnn, Bl + (bkk + 8) * BPITCH + bnn, rb1);
    };

    float acc[MT][4][4];
#pragma unroll
    for (int i = 0; i < MT; i++)
#pragma unroll
        for (int j = 0; j < 4; j++)
#pragma unroll
            for (int k = 0; k < 4; k++) acc[i][j][k] = 0.f;

    auto compute = [&](const float* base) {
        const float* Ah = base;
        const float* Al = base + ASTG;
        const float* Bh = base + 2 * ASTG;
        const float* Bl = Bh + BSTG;
        const int rw = wm * (MT * 16) + g;
        const int cw = wn * 32 + g;
#pragma unroll
        for (int ks = 0; ks < 2; ks++) {
            const int kb = ks * 8;
            uint32_t af[MT][4];
#pragma unroll
            for (int mt = 0; mt < MT; mt++) {
                const float* p = Ah + (size_t)(rw + mt * 16) * APITCH + kb + tg;
                af[mt][0] = __float_as_uint(p[0]);
                af[mt][1] = __float_as_uint(p[8 * APITCH]);
                af[mt][2] = __float_as_uint(p[4]);
                af[mt][3] = __float_as_uint(p[8 * APITCH + 4]);
            }
#pragma unroll
            for (int nt = 0; nt < 4; nt++) {
                const float* q  = Bh + (size_t)(kb + tg) * BPITCH + cw + nt * 8;
                const float* ql = Bl + (size_t)(kb + tg) * BPITCH + cw + nt * 8;
                uint32_t b0 = __float_as_uint(q[0]);
                uint32_t b1 = __float_as_uint(q[4 * BPITCH]);
                uint32_t l0 = __float_as_uint(ql[0]);
                uint32_t l1 = __float_as_uint(ql[4 * BPITCH]);
#pragma unroll
                for (int mt = 0; mt < MT; mt++) {
                    mma8(acc[mt][nt], af[mt], l0, l1);
                    mma8(acc[mt][nt], af[mt], b0, b1);
                }
            }
#pragma unroll
            for (int mt = 0; mt < MT; mt++) {
                const float* p = Al + (size_t)(rw + mt * 16) * APITCH + kb + tg;
                af[mt][0] = __float_as_uint(p[0]);
                af[mt][1] = __float_as_uint(p[8 * APITCH]);
                af[mt][2] = __float_as_uint(p[4]);
                af[mt][3] = __float_as_uint(p[8 * APITCH + 4]);
            }
#pragma unroll
            for (int nt = 0; nt < 4; nt++) {
                const float* q = Bh + (size_t)(kb + tg) * BPITCH + cw + nt * 8;
                uint32_t b0 = __float_as_uint(q[0]);
                uint32_t b1 = __float_as_uint(q[4 * BPITCH]);
#pragma unroll
                for (int mt = 0; mt < MT; mt++)
                    mma8(acc[mt][nt], af[mt], b0, b1);
            }
        }
    };

    const int nIter = K / 16;
    ldg(0);
    split_store(smx);
    __syncthreads();
    for (int it = 0; it < nIter; it++) {
        const int cur = it & 1;
        if (it + 1 < nIter) ldg((it + 1) * 16);
        compute(smx + cur * STAGE);
        if (it + 1 < nIter) split_store(smx + (cur ^ 1) * STAGE);
        __syncthreads();
    }

#pragma unroll
    for (int mt = 0; mt < MT; mt++) {
        int r0 = rowBase + wm * (MT * 16) + mt * 16 + g;
        float s0 = Sc ? Sc[(size_t)r0 * scaleStride] : 1.0f;
        float s1 = Sc ? Sc[(size_t)(r0 + 8) * scaleStride] : 1.0f;
#pragma unroll
        for (int nt = 0; nt < 4; nt++) {
            int cc = colBase + wn * 32 + nt * 8 + 2 * tg;
            float2 v0, v1;
            v0.x = acc[mt][nt][0] * s0; v0.y = acc[mt][nt][1] * s0;
            v1.x = acc[mt][nt][2] * s1; v1.y = acc[mt][nt][3] * s1;
            *reinterpret_cast<float2*>(C + (size_t)r0 * ldc + cc)       = v0;
            *reinterpret_cast<float2*>(C + (size_t)(r0 + 8) * ldc + cc) = v1;
        }
    }
}

// -------------------- fourier via tf32 3x mma ------------------------------
// One block: 128 (b,n,h)-rows x all 128 m for ONE side (blockIdx.y: 0=q,1=k).
// A[row][d] = DN * (s*pp + side*o*s*sp), K=64 resident in smem (single shot).
// B[k=d][n=m] = proj[m][d]. Epilogue: sincos -> out[row][m]=sin, [m+128]=cos.
__global__ __launch_bounds__(256) void fourier_mma(
    const float* __restrict__ pp, const float* __restrict__ sp,
    const float* __restrict__ scale, const float* __restrict__ offs,
    const float* __restrict__ proj, float* __restrict__ qout, float* __restrict__ kout)
{
    constexpr int AP = 68;    // A pitch: (68g+tg)%32 = 4g+tg -> conflict-free frags
    constexpr int BP = 136;   // B pitch: (136tg+g)%32 = 8tg+g -> conflict-free frags
    extern __shared__ float sm[];
    float* Ah = sm;                 // 128*68
    float* Al = Ah + 128 * AP;
    float* Bh = Al + 128 * AP;      // 64*136
    float* Bl = Bh + 64 * BP;

    const float DN    = 0.35355339059327378f;   // 64^-0.25
    const float RATIO = 0.08838834764831845f;   // 128^-0.5

    const int tid  = threadIdx.x;
    const int side = blockIdx.y;
    const size_t rbase = (size_t)blockIdx.x * 128;

    // B = proj^T, split hi/lo (one-time per block; proj is L2-resident)
    for (int i = tid; i < M_ * DH_; i += 256) {
        int m = i >> 6, d = i & 63;
        float h, l; split_tf32(proj[i], h, l);
        Bh[d * BP + m] = h;
        Bl[d * BP + m] = l;
    }

    // A load: combine pos/slope with per-head scale/offset, fold DN, split
#pragma unroll
    for (int t = 0; t < 8; t++) {
        int f   = tid + t * 256;
        int row = f >> 4;
        int d4  = (f & 15) * 4;
        size_t rid = rbase + row;
        int hh = (int)(rid & (H_ - 1));
        float s = DN * scale[hh];
        float4 v = *reinterpret_cast<const float4*>(pp + rid * DH_ + d4);
        float4 a;
        if (side) {
            float os = offs[hh] * s;
            float4 w = *reinterpret_cast<const float4*>(sp + rid * DH_ + d4);
            a.x = fmaf(os, w.x, s * v.x);
            a.y = fmaf(os, w.y, s * v.y);
            a.z = fmaf(os, w.z, s * v.z);
            a.w = fmaf(os, w.w, s * v.w);
        } else {
            a.x = s * v.x; a.y = s * v.y; a.z = s * v.z; a.w = s * v.w;
        }
        float4 h, l;
        split_tf32(a.x, h.x, l.x); split_tf32(a.y, h.y, l.y);
        split_tf32(a.z, h.z, l.z); split_tf32(a.w, h.w, l.w);
        *reinterpret_cast<float4*>(Ah + row * AP + d4) = h;
        *reinterpret_cast<float4*>(Al + row * AP + d4) = l;
    }
    __syncthreads();

    const int warp = tid >> 5, lane = tid & 31;
    const int g = lane >> 2, tg = lane & 3;
    const int wm = warp >> 2, wn = warp & 3;   // 2 x 4 warp grid, tile 64x32
    const int rw = wm * 64 + g;
    const int cw = wn * 32 + g;

    float acc[4][4][4];
#pragma unroll
    for (int i = 0; i < 4; i++)
#pragma unroll
        for (int j = 0; j < 4; j++)
#pragma unroll
            for (int k = 0; k < 4; k++) acc[i][j][k] = 0.f;

#pragma unroll
    for (int ks = 0; ks < 8; ks++) {
        const int kb = ks * 8;
        uint32_t afh[4][4], afl[4][4];
#pragma unroll
        for (int mt = 0; mt < 4; mt++) {
            const float* p  = Ah + (size_t)(rw + mt * 16) * AP + kb + tg;
            const float* pl = Al + (size_t)(rw + mt * 16) * AP + kb + tg;
            afh[mt][0] = __float_as_uint(p[0]);
            afh[mt][1] = __float_as_uint(p[8 * AP]);
            afh[mt][2] = __float_as_uint(p[4]);
            afh[mt][3] = __float_as_uint(p[8 * AP + 4]);
            afl[mt][0] = __float_as_uint(pl[0]);
            afl[mt][1] = __float_as_uint(pl[8 * AP]);
            afl[mt][2] = __float_as_uint(pl[4]);
            afl[mt][3] = __float_as_uint(pl[8 * AP + 4]);
        }
#pragma unroll
        for (int nt = 0; nt < 4; nt++) {
            const float* q  = Bh + (size_t)(kb + tg) * BP + cw + nt * 8;
            const float* ql = Bl + (size_t)(kb + tg) * BP + cw + nt * 8;
            uint32_t b0 = __float_as_uint(q[0]);
            uint32_t b1 = __float_as_uint(q[4 * BP]);
            uint32_t l0 = __float_as_uint(ql[0]);
            uint32_t l1 = __float_as_uint(ql[4 * BP]);
#pragma unroll
            for (int mt = 0; mt < 4; mt++) {
                mma8(acc[mt][nt], afh[mt], l0, l1);
                mma8(acc[mt][nt], afh[mt], b0, b1);
                mma8(acc[mt][nt], afl[mt], b0, b1);
            }
        }
    }

    float* outB = side ? kout : qout;
#pragma unroll
    for (int mt = 0; mt < 4; mt++) {
        size_t r0 = rbase + wm * 64 + mt * 16 + g;
#pragma unroll
        for (int nt = 0; nt < 4; nt++) {
            int col = wn * 32 + nt * 8 + 2 * tg;
            float s0, c0, s1, c1, s2, c2, s3, c3;
            fast_sincos(acc[mt][nt][0], s0, c0);
            fast_sincos(acc[mt][nt][1], s1, c1);
            fast_sincos(acc[mt][nt][2], s2, c2);
            fast_sincos(acc[mt][nt][3], s3, c3);
            float* p0 = outB + r0 * TWOM_ + col;
            float* p1 = outB + (r0 + 8) * TWOM_ + col;
            *reinterpret_cast<float2*>(p0)       = make_float2(RATIO * s0, RATIO * s1);
            *reinterpret_cast<float2*>(p0 + M_)  = make_float2(RATIO * c0, RATIO * c1);
            *reinterpret_cast<float2*>(p1)       = make_float2(RATIO * s2, RATIO * s3);
            *reinterpret_cast<float2*>(p1 + M_)  = make_float2(RATIO * c2, RATIO * c3);
        }
    }
}

// -------------------- slope norms ------------------------------------------
__global__ __launch_bounds__(256) void norm_kernel(
    const float* __restrict__ sp, float* __restrict__ norm)
{
    int row  = blockIdx.x * 8 + (threadIdx.x >> 5);
    int lane = threadIdx.x & 31;
    const float* p = sp + (size_t)row * DH_;
    float a = p[lane], b = p[lane + 32];
    float v = a * a + b * b;
#pragma unroll
    for (int off = 16; off > 0; off >>= 1)
        v += __shfl_xor_sync(0xffffffff, v, off);
    if (lane == 0)
        norm[row] = sqrtf(v) * (1.0f / (float)N_);
}

// -------------------- GEMM TN (split-K, fp32 SIMT): kvs --------------------
__global__ __launch_bounds__(128) void gemm_tn_kernel(
    const float* __restrict__ A, const float* __restrict__ Bm, float* __restrict__ Cpart,
    int K, int lda, int ldb,
    long sAb, long sAh, long sBb, long sBh, long sCb, long sCh, int Hdim)
{
    int z = blockIdx.z;
    int zb = z / Hdim, zh = z % Hdim;
    A  += (size_t)zb * sAb + (size_t)zh * sAh;
    Bm += (size_t)zb * sBb + (size_t)zh * sBh;
    float* C = Cpart + (size_t)blockIdx.y * KVS_SZ + (size_t)zb * sCb + (size_t)zh * sCh;

    __shared__ float As[16][64];
    __shared__ float Bs[16][64];

    int tid = threadIdx.x;
    int tx = tid & 7;
    int ty = tid >> 3;
    int m0 = blockIdx.x * 64;

    int kLen   = K / KSPLIT;
    int kStart = blockIdx.y * kLen;

    float acc[4][8];
#pragma unroll
    for (int i = 0; i < 4; i++)
#pragma unroll
        for (int j = 0; j < 8; j++) acc[i][j] = 0.f;

    for (int k0 = kStart; k0 < kStart + kLen; k0 += 16) {
#pragma unroll
        for (int t = 0; t < 2; t++) {
            int f  = tid + t * 128;
            int kk = f >> 4;
            int m4 = (f & 15) * 4;
            *reinterpret_cast<float4*>(&As[kk][m4]) =
                *reinterpret_cast<const float4*>(A + (size_t)(k0 + kk) * lda + m0 + m4);
        }
#pragma unroll
        for (int t = 0; t < 2; t++) {
            int f  = tid + t * 128;
            int kk = f >> 4;
            int n4 = (f & 15) * 4;
            *reinterpret_cast<float4*>(&Bs[kk][n4]) =
                *reinterpret_cast<const float4*>(Bm + (size_t)(k0 + kk) * ldb + n4);
        }
        __syncthreads();
#pragma unroll
        for (int kk = 0; kk < 16; kk++) {
            float a[4], b[8];
            *reinterpret_cast<float4*>(&a[0]) = *reinterpret_cast<float4*>(&As[kk][ty * 4]);
            *reinterpret_cast<float4*>(&b[0]) = *reinterpret_cast<float4*>(&Bs[kk][tx * 8]);
            *reinterpret_cast<float4*>(&b[4]) = *reinterpret_cast<float4*>(&Bs[kk][tx * 8 + 4]);
#pragma unroll
            for (int i = 0; i < 4; i++)
#pragma unroll
                for (int j = 0; j < 8; j++)
                    acc[i][j] = fmaf(a[i], b[j], acc[i][j]);
        }
        __syncthreads();
    }

#pragma unroll
    for (int i = 0; i < 4; i++) {
        float* cp = C + (size_t)(m0 + ty * 4 + i) * DH_ + tx * 8;
        float4 o0, o1;
        o0.x = acc[i][0]; o0.y = acc[i][1]; o0.z = acc[i][2]; o0.w = acc[i][3];
        o1.x = acc[i][4]; o1.y = acc[i][5]; o1.z = acc[i][6]; o1.w = acc[i][7];
        *reinterpret_cast<float4*>(cp)     = o0;
        *reinterpret_cast<float4*>(cp + 4) = o1;
    }
}

__global__ void kvs_reduce_kernel() {
    int i = blockIdx.x * 256 + threadIdx.x;
    if (i < KVS_SZ) {
        float s = 0.f;
#pragma unroll
        for (int p = 0; p < KSPLIT; p++) s += g_kvs_part[(size_t)p * KVS_SZ + i];
        g_kvs[i] = s;
    }
}

// -------------------- launch -----------------------------------------------
extern "C" void kernel_launch(void* const* d_in, const int* in_sizes, int n_in,
                              void* d_out, int out_size)
{
    (void)in_sizes; (void)n_in; (void)out_size;
    const float* src  = (const float*)d_in[0];
    const float* pf   = (const float*)d_in[1];
    const float* pfs  = (const float*)d_in[2];
    const float* vw   = (const float*)d_in[3];
    const float* pw   = (const float*)d_in[4];
    const float* sc   = (const float*)d_in[5];
    const float* off  = (const float*)d_in[6];
    const float* ow   = (const float*)d_in[7];
    const float* proj = (const float*)d_in[8];

    float* out  = (float*)d_out;
    float* qout = out + PROJSZ;
    float* kout = qout + QKPRSZ;

    float *val, *pp, *sp, *nr, *kvs, *kvsp, *av;
    cudaGetSymbolAddress((void**)&val,  g_val);
    cudaGetSymbolAddress((void**)&pp,   g_pp);
    cudaGetSymbolAddress((void**)&sp,   g_sp);
    cudaGetSymbolAddress((void**)&nr,   g_norm);
    cudaGetSymbolAddress((void**)&kvs,  g_kvs);
    cudaGetSymbolAddress((void**)&kvsp, g_kvs_part);
    cudaGetSymbolAddress((void**)&av,   g_av);

    const int SM128 = (2 * 128 * 20 + 2 * 16 * 136) * 4 * 2;  // 75776 B
    const int SM64  = (2 * 128 * 20 + 2 * 16 * 72)  * 4 * 2;  // 59392 B
    const int SMF   = (2 * 128 * 68 + 2 * 64 * 136) * 4;      // 139264 B
    cudaFuncSetAttribute(gemm_tf32_nn<128>, cudaFuncAttributeMaxDynamicSharedMemorySize, SM128);
    cudaFuncSetAttribute(gemm_tf32_nn<64>,  cudaFuncAttributeMaxDynamicSharedMemorySize, SM64);
    cudaFuncSetAttribute(fourier_mma,       cudaFuncAttributeMaxDynamicSharedMemorySize, SMF);

    dim3 gBig(ROWS_TOT / 128, D_ / 128, 1);

    // 1-3: projections (tf32 tensor)
    gemm_tf32_nn<128><<<gBig, 256, SM128>>>(src, vw, val, D_, D_, D_, D_,
                                            0,0,0,0,0,0, 1, nullptr, 0,0,0);
    gemm_tf32_nn<128><<<gBig, 256, SM128>>>(pf,  pw, pp,  D_, D_, D_, D_,
                                            0,0,0,0,0,0, 1, nullptr, 0,0,0);
    gemm_tf32_nn<128><<<gBig, 256, SM128>>>(pfs, pw, sp,  D_, D_, D_, D_,
                                            0,0,0,0,0,0, 1, nullptr, 0,0,0);

    // 4: fourier features via tensor mma (posprep fused into A-load)
    {
        dim3 g(BNH / 128, 2, 1);   // y: 0=q', 1=k'
        fourier_mma<<<g, 256, SMF>>>(pp, sp, sc, off, proj, qout, kout);
    }

    // 4b: slope norms
    norm_kernel<<<BNH / 8, 256>>>(sp, nr);

    // 5: kvs = k'^T @ V per (b,h): split-K partials + deterministic reduce
    {
        long sAb = (long)N_ * H_ * TWOM_;
        long sAh = TWOM_;
        long sBb = (long)N_ * H_ * DH_;
        long sBh = DH_;
        long sCb = (long)H_ * TWOM_ * DH_;
        long sCh = (long)TWOM_ * DH_;
        dim3 g(TWOM_ / 64, KSPLIT, B_ * H_);
        gemm_tn_kernel<<<g, 128>>>(kout, val, kvsp, N_, (long)H_ * TWOM_, (long)H_ * DH_,
                                   sAb, sAh, sBb, sBh, sCb, sCh, H_);
        kvs_reduce_kernel<<<(KVS_SZ + 255) / 256, 256>>>();
    }

    // 6: av = norm * (q' @ kvs) per (b,h) (tf32 tensor, BN=64)
    {
        long sAb = (long)N_ * H_ * TWOM_;
        long sAh = TWOM_;
        long sBb = (long)H_ * TWOM_ * DH_;
        long sBh = (long)TWOM_ * DH_;
        long sCb = (long)N_ * H_ * DH_;
        long sCh = DH_;
        long sSb = (long)N_ * H_;
        long sSh = 1;
        dim3 g(N_ / 128, 1, B_ * H_);
        gemm_tf32_nn<64><<<g, 256, SM64>>>(qout, kvs, av, TWOM_,
                                           H_ * TWOM_, DH_, H_ * DH_,
                                           sAb, sAh, sBb, sBh, sCb, sCh, H_,
                                           nr, sSb, sSh, H_);
    }

    // 7: out = av_flat @ output_weight (tf32 tensor)
    gemm_tf32_nn<128><<<gBig, 256, SM128>>>(av, ow, out, D_, D_, D_, D_,
                                            0,0,0,0,0,0, 1, nullptr, 0,0,0);
}